// round 6
// baseline (speedup 1.0000x reference)
#include <cuda_runtime.h>
#include <cstdint>
#include <math.h>

#define N_NODES 50000
#define N_EDGES 800000
#define D0 1024
#define D1 512
#define D2 128
#define DOUT 14

// ---------------- scratch (device globals; no allocs allowed) ----------------
__device__ float g_deg[N_NODES];
__device__ float g_dis[N_NODES];
__device__ int   g_cnt[N_NODES];
__device__ int   g_rowptr[N_NODES + 1];
__device__ int   g_src[N_EDGES];
__device__ float g_wgt[N_EDGES];
__device__ float g_h1[(size_t)N_NODES * D1];   // X @ W1
__device__ float g_a1[(size_t)N_NODES * D1];   // relu(norm-agg + b1)
__device__ float g_h2[(size_t)N_NODES * D2];   // a1 @ W2
__device__ int   g_is64;

// ---------------- edge-index dtype detection (int64 vs int32) ----------------
// int64 data with values < 50000 has all-zero high words. Parallel scan:
// 32 lanes x 32 independent (unrolled, MLP-rich) loads, ballot-reduce.
__global__ void detect_idx_kernel(const void* eidx) {
    int lane = threadIdx.x & 31;
    const int* p = (const int*)eidx;
    int bad = 0;
#pragma unroll
    for (int k = 0; k < 32; k++) {
        bad |= p[2 * (k * 32 + lane) + 1];
    }
    unsigned m = __ballot_sync(0xffffffffu, bad != 0);
    if (lane == 0) g_is64 = (m == 0) ? 1 : 0;
}

__device__ __forceinline__ int get_idx(const void* base, long i) {
    if (g_is64) return (int)((const long long*)base)[i];
    return ((const int*)base)[i];
}

// ---------------- degree / normalization / CSR build ----------------
__global__ void init_kernel() {
    int i = blockIdx.x * blockDim.x + threadIdx.x;
    if (i < N_NODES) { g_deg[i] = 1.0f; g_cnt[i] = 0; }
}

__global__ void edge_deg_kernel(const void* eidx, const float* __restrict__ ew) {
    int e = blockIdx.x * blockDim.x + threadIdx.x;
    if (e < N_EDGES) {
        int c = get_idx(eidx, (long)N_EDGES + e);
        atomicAdd(&g_deg[c], ew[e]);
        atomicAdd(&g_cnt[c], 1);
    }
}

__global__ void dis_kernel() {
    int i = blockIdx.x * blockDim.x + threadIdx.x;
    if (i < N_NODES) g_dis[i] = rsqrtf(g_deg[i]);
}

__global__ void scan_kernel() {
    __shared__ int part[1024];
    int tid = threadIdx.x;
    const int chunk = (N_NODES + 1023) / 1024;
    int start = tid * chunk;
    int end = start + chunk; if (end > N_NODES) end = N_NODES;
    int s = 0;
    for (int i = start; i < end; i++) s += g_cnt[i];
    part[tid] = s;
    __syncthreads();
    if (tid == 0) {
        int run = 0;
        for (int i = 0; i < 1024; i++) { int v = part[i]; part[i] = run; run += v; }
        g_rowptr[N_NODES] = run;
    }
    __syncthreads();
    int run = part[tid];
    for (int i = start; i < end; i++) {
        g_rowptr[i] = run;
        run += g_cnt[i];
        g_cnt[i] = 0;
    }
}

__global__ void scatter_kernel(const void* eidx, const float* __restrict__ ew) {
    int e = blockIdx.x * blockDim.x + threadIdx.x;
    if (e < N_EDGES) {
        int r = get_idx(eidx, e);
        int c = get_idx(eidx, (long)N_EDGES + e);
        int pos = g_rowptr[c] + atomicAdd(&g_cnt[c], 1);
        g_src[pos] = r;
        g_wgt[pos] = ew[e] * g_dis[r];
    }
}

// ---------------- tf32 tensor-core GEMM, cp.async 3-stage, BK=16 ----------------
// BM=128, BN=128, BK=16; 256 threads = 8 warps (4x2); warp tile 32x64.
// Raw fp32 fed to mma.tf32 (HW truncates mantissa) — no cvt anywhere.
#define BM 128
#define BN 128
#define BK 16
#define AS_STRIDE 20            // BK+4
#define BS_STRIDE 136           // BN+8
#define AS_SZ (BM * AS_STRIDE)  // 2560 floats
#define BS_SZ (BK * BS_STRIDE)  // 2176 floats
#define STAGE_SZ (AS_SZ + BS_SZ)            // 4736 floats
#define GEMM_SMEM_BYTES (3 * STAGE_SZ * 4)  // 56832 B

__device__ __forceinline__ void mma_tf32(float* d, const float* a, const float* b) {
    asm volatile(
        "mma.sync.aligned.m16n8k8.row.col.f32.tf32.tf32.f32 "
        "{%0,%1,%2,%3}, {%4,%5,%6,%7}, {%8,%9}, {%0,%1,%2,%3};"
        : "+f"(d[0]), "+f"(d[1]), "+f"(d[2]), "+f"(d[3])
        : "f"(a[0]), "f"(a[1]), "f"(a[2]), "f"(a[3]),
          "f"(b[0]), "f"(b[1]));
}

__device__ __forceinline__ void cp_async16(float* smem_ptr, const float* gptr, int srcsize) {
    unsigned int sa = (unsigned int)__cvta_generic_to_shared(smem_ptr);
    asm volatile("cp.async.cg.shared.global [%0], [%1], 16, %2;\n"
                 :: "r"(sa), "l"(gptr), "r"(srcsize));
}

// Load one BK=16 stage: per thread 2 A + 2 B cp.asyncs.
__device__ __forceinline__ void load_stage(
    const float* __restrict__ A, const float* __restrict__ B,
    int M, int K, int N, int rowBase, int colBase, int k0,
    float* As, float* Bs, int tid)
{
    int ar  = tid >> 2;          // 0..63
    int ac4 = (tid & 3) * 4;     // 0,4,8,12
    int bk  = tid >> 5;          // 0..7
    int bn4 = (tid & 31) * 4;    // 0..124
#pragma unroll
    for (int p = 0; p < 2; p++) {
        int m = p * 64 + ar;
        int gr = rowBase + m;
        int sz = (gr < M) ? 16 : 0;
        int grc = (gr < M) ? gr : 0;
        cp_async16(&As[m * AS_STRIDE + ac4], A + (size_t)grc * K + k0 + ac4, sz);
    }
#pragma unroll
    for (int p = 0; p < 2; p++) {
        int kk = p * 8 + bk;
        cp_async16(&Bs[kk * BS_STRIDE + bn4], B + (size_t)(k0 + kk) * N + colBase + bn4, 16);
    }
}

__global__ __launch_bounds__(256, 2)
void tf32gemm(const float* __restrict__ A, const float* __restrict__ B,
              float* __restrict__ C, int M, int K, int N) {
    extern __shared__ float smem_dyn[];

    int tid = threadIdx.x;
    int warp = tid >> 5, lane = tid & 31;
    int g = lane >> 2, t = lane & 3;
    int wm = (warp >> 1) * 32;
    int wn = (warp & 1) * 64;

    int rowBase = blockIdx.y * BM;
    int colBase = blockIdx.x * BN;

    float acc[2][8][4];
#pragma unroll
    for (int mi = 0; mi < 2; mi++)
#pragma unroll
        for (int ni = 0; ni < 8; ni++)
#pragma unroll
            for (int r = 0; r < 4; r++) acc[mi][ni][r] = 0.f;

    float* a_cur = smem_dyn;
    float* a_nxt = smem_dyn + STAGE_SZ;
    float* a_spr = smem_dyn + 2 * STAGE_SZ;
    float* b_cur = a_cur + AS_SZ;
    float* b_nxt = a_nxt + AS_SZ;
    float* b_spr = a_spr + AS_SZ;

    int niter = K / BK;

    // prologue: stages 0 and 1
    load_stage(A, B, M, K, N, rowBase, colBase, 0, a_cur, b_cur, tid);
    asm volatile("cp.async.commit_group;\n");
    if (niter > 1) {
        load_stage(A, B, M, K, N, rowBase, colBase, BK, a_nxt, b_nxt, tid);
        asm volatile("cp.async.commit_group;\n");
    }

    for (int i = 0; i < niter; i++) {
        if (i + 2 < niter) {
            load_stage(A, B, M, K, N, rowBase, colBase, (i + 2) * BK, a_spr, b_spr, tid);
            asm volatile("cp.async.commit_group;\n");
            asm volatile("cp.async.wait_group 2;\n");
        } else if (i + 1 < niter) {
            asm volatile("cp.async.wait_group 1;\n");
        } else {
            asm volatile("cp.async.wait_group 0;\n");
        }
        __syncthreads();

#pragma unroll
        for (int kk = 0; kk < BK; kk += 8) {
            float a[2][4];
#pragma unroll
            for (int mi = 0; mi < 2; mi++) {
                int row = wm + mi * 16;
                a[mi][0] = a_cur[(row + g    ) * AS_STRIDE + kk + t    ];
                a[mi][1] = a_cur[(row + g + 8) * AS_STRIDE + kk + t    ];
                a[mi][2] = a_cur[(row + g    ) * AS_STRIDE + kk + t + 4];
                a[mi][3] = a_cur[(row + g + 8) * AS_STRIDE + kk + t + 4];
            }
            float b[8][2];
#pragma unroll
            for (int ni = 0; ni < 8; ni++) {
                int col = wn + ni * 8;
                b[ni][0] = b_cur[(kk + t    ) * BS_STRIDE + col + g];
                b[ni][1] = b_cur[(kk + t + 4) * BS_STRIDE + col + g];
            }
#pragma unroll
            for (int mi = 0; mi < 2; mi++)
#pragma unroll
                for (int ni = 0; ni < 8; ni++)
                    mma_tf32(acc[mi][ni], a[mi], b[ni]);
        }
        __syncthreads();

        // rotate stages
        float* ta = a_cur; a_cur = a_nxt; a_nxt = a_spr; a_spr = ta;
        float* tb = b_cur; b_cur = b_nxt; b_nxt = b_spr; b_spr = tb;
    }

    // epilogue
#pragma unroll
    for (int mi = 0; mi < 2; mi++) {
        int row0 = rowBase + wm + mi * 16 + g;
        int row1 = row0 + 8;
#pragma unroll
        for (int ni = 0; ni < 8; ni++) {
            int col = colBase + wn + ni * 8 + t * 2;
            if (row0 < M)
                *(float2*)(C + (size_t)row0 * N + col) =
                    make_float2(acc[mi][ni][0], acc[mi][ni][1]);
            if (row1 < M)
                *(float2*)(C + (size_t)row1 * N + col) =
                    make_float2(acc[mi][ni][2], acc[mi][ni][3]);
        }
    }
}

// ---------------- aggregation layer 1: 512 features, 1 warp / node ----------------
__global__ __launch_bounds__(256)
void agg1_kernel(const float* __restrict__ b1) {
    int node = blockIdx.x * 8 + (threadIdx.x >> 5);
    if (node >= N_NODES) return;
    int lane = threadIdx.x & 31;
    const float4* h = (const float4*)g_h1;
    float dc = g_dis[node];

    float4 acc[4];
#pragma unroll
    for (int i = 0; i < 4; i++) {
        float4 v = h[(size_t)node * 128 + lane + i * 32];
        acc[i] = make_float4(v.x * dc, v.y * dc, v.z * dc, v.w * dc);
    }
    int beg = g_rowptr[node], end = g_rowptr[node + 1];
    for (int e = beg; e < end; e++) {
        int r = g_src[e];
        float w = g_wgt[e];
        const float4* hr = h + (size_t)r * 128;
#pragma unroll
        for (int i = 0; i < 4; i++) {
            float4 v = hr[lane + i * 32];
            acc[i].x += w * v.x; acc[i].y += w * v.y;
            acc[i].z += w * v.z; acc[i].w += w * v.w;
        }
    }
    float4* out = (float4*)g_a1;
    const float4* bb4 = (const float4*)b1;
#pragma unroll
    for (int i = 0; i < 4; i++) {
        float4 bb = bb4[lane + i * 32];
        float4 o;
        o.x = fmaxf(dc * acc[i].x + bb.x, 0.f);
        o.y = fmaxf(dc * acc[i].y + bb.y, 0.f);
        o.z = fmaxf(dc * acc[i].z + bb.z, 0.f);
        o.w = fmaxf(dc * acc[i].w + bb.w, 0.f);
        out[(size_t)node * 128 + lane + i * 32] = o;
    }
}

// ---------------- aggregation layer 2 fused with FC(128->14)+sigmoid ----------------
__global__ __launch_bounds__(256)
void agg2_fc_kernel(const float* __restrict__ b2, const float* __restrict__ Wfc,
                    const float* __restrict__ bfc, float* __restrict__ out) {
    __shared__ float sh[8][128];
    __shared__ float sWfc[D2 * DOUT];
    for (int i = threadIdx.x; i < D2 * DOUT; i += blockDim.x) sWfc[i] = Wfc[i];
    __syncthreads();

    int wid = threadIdx.x >> 5;
    int lane = threadIdx.x & 31;
    int node = blockIdx.x * 8 + wid;

    if (node < N_NODES) {
        const float4* h = (const float4*)g_h2;
        float dc = g_dis[node];
        float4 v = h[(size_t)node * 32 + lane];
        float4 acc = make_float4(v.x * dc, v.y * dc, v.z * dc, v.w * dc);
        int beg = g_rowptr[node], end = g_rowptr[node + 1];
        for (int e = beg; e < end; e++) {
            int r = g_src[e];
            float w = g_wgt[e];
            float4 u = h[(size_t)r * 32 + lane];
            acc.x += w * u.x; acc.y += w * u.y; acc.z += w * u.z; acc.w += w * u.w;
        }
        float4 bb = ((const float4*)b2)[lane];
        sh[wid][lane * 4 + 0] = fmaxf(dc * acc.x + bb.x, 0.f);
        sh[wid][lane * 4 + 1] = fmaxf(dc * acc.y + bb.y, 0.f);
        sh[wid][lane * 4 + 2] = fmaxf(dc * acc.z + bb.z, 0.f);
        sh[wid][lane * 4 + 3] = fmaxf(dc * acc.w + bb.w, 0.f);
    }
    __syncwarp();
    if (node < N_NODES && lane < DOUT) {
        float s = bfc[lane];
#pragma unroll 8
        for (int d = 0; d < D2; d++) s += sh[wid][d] * sWfc[d * DOUT + lane];
        out[(size_t)node * DOUT + lane] = 1.f / (1.f + expf(-s));
    }
}

// ---------------- launch ----------------
// GEMM1 placed at our launch #4: profiled launch = ours #4 (2 harness
// launches precede; dis_kernel at #4 was captured in every prior round).
extern "C" void kernel_launch(void* const* d_in, const int* in_sizes, int n_in,
                              void* d_out, int out_size) {
    const float* x   = (const float*)d_in[0];
    const void*  eix = d_in[1];
    const float* ew  = (const float*)d_in[2];
    const float* W1  = (const float*)d_in[3];
    const float* b1  = (const float*)d_in[4];
    const float* W2  = (const float*)d_in[5];
    const float* b2  = (const float*)d_in[6];
    const float* Wfc = (const float*)d_in[7];
    const float* bfc = (const float*)d_in[8];
    float* out = (float*)d_out;

    float *h1p, *a1p, *h2p;
    cudaGetSymbolAddress((void**)&h1p, g_h1);
    cudaGetSymbolAddress((void**)&a1p, g_a1);
    cudaGetSymbolAddress((void**)&h2p, g_h2);

    cudaFuncSetAttribute(tf32gemm, cudaFuncAttributeMaxDynamicSharedMemorySize,
                         GEMM_SMEM_BYTES);

    const int TB = 256;
    detect_idx_kernel<<<1, 32>>>(eix);                              // 1
    init_kernel<<<(N_NODES + TB - 1) / TB, TB>>>();                 // 2
    edge_deg_kernel<<<(N_EDGES + TB - 1) / TB, TB>>>(eix, ew);      // 3

    dim3 g1(D1 / BN, (N_NODES + BM - 1) / BM);
    tf32gemm<<<g1, 256, GEMM_SMEM_BYTES>>>(x, W1, h1p, N_NODES, D0, D1);  // 4 <- ncu

    dis_kernel<<<(N_NODES + TB - 1) / TB, TB>>>();                  // 5
    scan_kernel<<<1, 1024>>>();                                     // 6
    scatter_kernel<<<(N_EDGES + TB - 1) / TB, TB>>>(eix, ew);       // 7

    agg1_kernel<<<(N_NODES + 7) / 8, 256>>>(b1);                    // 8

    dim3 g2(D2 / BN, (N_NODES + BM - 1) / BM);
    tf32gemm<<<g2, 256, GEMM_SMEM_BYTES>>>(a1p, W2, h2p, N_NODES, D1, D2);  // 9

    agg2_fc_kernel<<<(N_NODES + 7) / 8, 256>>>(b2, Wfc, bfc, out);  // 10
}

// round 7
// speedup vs baseline: 1.0440x; 1.0440x over previous
#include <cuda_runtime.h>
#include <cstdint>
#include <math.h>

#define N_NODES 50000
#define N_EDGES 800000
#define D0 1024
#define D1 512
#define D2 128
#define DOUT 14

// ---------------- scratch (device globals; no allocs allowed) ----------------
__device__ float g_deg[N_NODES];
__device__ float g_dis[N_NODES];
__device__ int   g_cnt[N_NODES];
__device__ int   g_rowptr[N_NODES + 1];
__device__ int   g_src[N_EDGES];
__device__ float g_wgt[N_EDGES];
__device__ float g_h1[(size_t)N_NODES * D1];   // X @ W1
__device__ float g_a1[(size_t)N_NODES * D1];   // relu(norm-agg + b1)
__device__ float g_h2[(size_t)N_NODES * D2];   // a1 @ W2
__device__ int   g_is64;

// ---------------- edge-index dtype detection (int64 vs int32) ----------------
__global__ void detect_idx_kernel(const void* eidx) {
    int lane = threadIdx.x & 31;
    const int* p = (const int*)eidx;
    int bad = 0;
#pragma unroll
    for (int k = 0; k < 32; k++) {
        bad |= p[2 * (k * 32 + lane) + 1];
    }
    unsigned m = __ballot_sync(0xffffffffu, bad != 0);
    if (lane == 0) g_is64 = (m == 0) ? 1 : 0;
}

__device__ __forceinline__ int get_idx(const void* base, long i) {
    if (g_is64) return (int)((const long long*)base)[i];
    return ((const int*)base)[i];
}

// ---------------- degree / normalization / CSR build ----------------
__global__ void init_kernel() {
    int i = blockIdx.x * blockDim.x + threadIdx.x;
    if (i < N_NODES) { g_deg[i] = 1.0f; g_cnt[i] = 0; }
}

__global__ void edge_deg_kernel(const void* eidx, const float* __restrict__ ew) {
    int e = blockIdx.x * blockDim.x + threadIdx.x;
    if (e < N_EDGES) {
        int c = get_idx(eidx, (long)N_EDGES + e);
        atomicAdd(&g_deg[c], ew[e]);
        atomicAdd(&g_cnt[c], 1);
    }
}

__global__ void dis_kernel() {
    int i = blockIdx.x * blockDim.x + threadIdx.x;
    if (i < N_NODES) g_dis[i] = rsqrtf(g_deg[i]);
}

__global__ void scan_kernel() {
    __shared__ int part[1024];
    int tid = threadIdx.x;
    const int chunk = (N_NODES + 1023) / 1024;
    int start = tid * chunk;
    int end = start + chunk; if (end > N_NODES) end = N_NODES;
    int s = 0;
    for (int i = start; i < end; i++) s += g_cnt[i];
    part[tid] = s;
    __syncthreads();
    if (tid == 0) {
        int run = 0;
        for (int i = 0; i < 1024; i++) { int v = part[i]; part[i] = run; run += v; }
        g_rowptr[N_NODES] = run;
    }
    __syncthreads();
    int run = part[tid];
    for (int i = start; i < end; i++) {
        g_rowptr[i] = run;
        run += g_cnt[i];
        g_cnt[i] = 0;
    }
}

__global__ void scatter_kernel(const void* eidx, const float* __restrict__ ew) {
    int e = blockIdx.x * blockDim.x + threadIdx.x;
    if (e < N_EDGES) {
        int r = get_idx(eidx, e);
        int c = get_idx(eidx, (long)N_EDGES + e);
        int pos = g_rowptr[c] + atomicAdd(&g_cnt[c], 1);
        g_src[pos] = r;
        g_wgt[pos] = ew[e] * g_dis[r];
    }
}

// ---------------- tf32 tensor-core GEMM, cp.async 4-stage, 1 barrier/iter ----
// BM=128, BN=128, BK=16; 256 threads = 8 warps (4x2); warp tile 32x64.
// Raw fp32 fed to mma.tf32 (HW truncates mantissa).
#define BM 128
#define BN 128
#define BK 16
#define STAGES 4
#define AS_STRIDE 20            // BK+4
#define BS_STRIDE 136           // BN+8
#define AS_SZ (BM * AS_STRIDE)  // 2560 floats
#define BS_SZ (BK * BS_STRIDE)  // 2176 floats
#define STAGE_SZ (AS_SZ + BS_SZ)                 // 4736 floats
#define GEMM_SMEM_BYTES (STAGES * STAGE_SZ * 4)  // 75776 B

__device__ __forceinline__ void mma_tf32(float* d, const float* a, const float* b) {
    asm volatile(
        "mma.sync.aligned.m16n8k8.row.col.f32.tf32.tf32.f32 "
        "{%0,%1,%2,%3}, {%4,%5,%6,%7}, {%8,%9}, {%0,%1,%2,%3};"
        : "+f"(d[0]), "+f"(d[1]), "+f"(d[2]), "+f"(d[3])
        : "f"(a[0]), "f"(a[1]), "f"(a[2]), "f"(a[3]),
          "f"(b[0]), "f"(b[1]));
}

__device__ __forceinline__ void cp_async16(float* smem_ptr, const float* gptr, int srcsize) {
    unsigned int sa = (unsigned int)__cvta_generic_to_shared(smem_ptr);
    asm volatile("cp.async.cg.shared.global [%0], [%1], 16, %2;\n"
                 :: "r"(sa), "l"(gptr), "r"(srcsize));
}

// Load one BK=16 stage: per thread 2 A + 2 B cp.asyncs.
__device__ __forceinline__ void load_stage(
    const float* __restrict__ A, const float* __restrict__ B,
    int M, int K, int N, int rowBase, int colBase, int k0,
    float* As, float* Bs, int tid)
{
    int ar  = tid >> 2;          // 0..63
    int ac4 = (tid & 3) * 4;     // 0,4,8,12
    int bk  = tid >> 5;          // 0..7
    int bn4 = (tid & 31) * 4;    // 0..124
#pragma unroll
    for (int p = 0; p < 2; p++) {
        int m = p * 64 + ar;
        int gr = rowBase + m;
        int sz = (gr < M) ? 16 : 0;
        int grc = (gr < M) ? gr : 0;
        cp_async16(&As[m * AS_STRIDE + ac4], A + (size_t)grc * K + k0 + ac4, sz);
    }
#pragma unroll
    for (int p = 0; p < 2; p++) {
        int kk = p * 8 + bk;
        cp_async16(&Bs[kk * BS_STRIDE + bn4], B + (size_t)(k0 + kk) * N + colBase + bn4, 16);
    }
}

__global__ __launch_bounds__(256, 2)
void tf32gemm(const float* __restrict__ A, const float* __restrict__ B,
              float* __restrict__ C, int M, int K, int N) {
    extern __shared__ float smem_dyn[];

    int tid = threadIdx.x;
    int warp = tid >> 5, lane = tid & 31;
    int g = lane >> 2, t = lane & 3;
    int wm = (warp >> 1) * 32;
    int wn = (warp & 1) * 64;

    int rowBase = blockIdx.y * BM;
    int colBase = blockIdx.x * BN;

    float acc[2][8][4];
#pragma unroll
    for (int mi = 0; mi < 2; mi++)
#pragma unroll
        for (int ni = 0; ni < 8; ni++)
#pragma unroll
            for (int r = 0; r < 4; r++) acc[mi][ni][r] = 0.f;

    int niter = K / BK;

    // prologue: fill stages 0..STAGES-2, one commit group each
#pragma unroll
    for (int p = 0; p < STAGES - 1; p++) {
        if (p < niter)
            load_stage(A, B, M, K, N, rowBase, colBase, p * BK,
                       smem_dyn + p * STAGE_SZ, smem_dyn + p * STAGE_SZ + AS_SZ, tid);
        asm volatile("cp.async.commit_group;\n");
    }

    int s_cur = 0;              // stage being computed
    int s_load = STAGES - 1;    // stage being filled this iteration

    for (int i = 0; i < niter; i++) {
        // stage i's group has exactly STAGES-2 newer groups committed -> wait
        asm volatile("cp.async.wait_group 2;\n");
        __syncthreads();

        // issue load for stage i+STAGES-1 (overwrites stage read at iter i-1;
        // safe: all threads passed this barrier after finishing that read)
        int inext = i + STAGES - 1;
        if (inext < niter)
            load_stage(A, B, M, K, N, rowBase, colBase, inext * BK,
                       smem_dyn + s_load * STAGE_SZ,
                       smem_dyn + s_load * STAGE_SZ + AS_SZ, tid);
        asm volatile("cp.async.commit_group;\n");  // commit every iter (may be empty)

        const float* As = smem_dyn + s_cur * STAGE_SZ;
        const float* Bs = As + AS_SZ;
#pragma unroll
        for (int kk = 0; kk < BK; kk += 8) {
            float a[2][4];
#pragma unroll
            for (int mi = 0; mi < 2; mi++) {
                int row = wm + mi * 16;
                a[mi][0] = As[(row + g    ) * AS_STRIDE + kk + t    ];
                a[mi][1] = As[(row + g + 8) * AS_STRIDE + kk + t    ];
                a[mi][2] = As[(row + g    ) * AS_STRIDE + kk + t + 4];
                a[mi][3] = As[(row + g + 8) * AS_STRIDE + kk + t + 4];
            }
#pragma unroll
            for (int h = 0; h < 2; h++) {     // chunked B: 8 live b regs, not 16
                float b[4][2];
#pragma unroll
                for (int nj = 0; nj < 4; nj++) {
                    int col = wn + (h * 4 + nj) * 8;
                    b[nj][0] = Bs[(kk + t    ) * BS_STRIDE + col + g];
                    b[nj][1] = Bs[(kk + t + 4) * BS_STRIDE + col + g];
                }
#pragma unroll
                for (int mi = 0; mi < 2; mi++)
#pragma unroll
                    for (int nj = 0; nj < 4; nj++)
                        mma_tf32(acc[mi][h * 4 + nj], a[mi], b[nj]);
            }
        }

        s_cur  = (s_cur  + 1 == STAGES) ? 0 : s_cur  + 1;
        s_load = (s_load + 1 == STAGES) ? 0 : s_load + 1;
    }

    // epilogue
#pragma unroll
    for (int mi = 0; mi < 2; mi++) {
        int row0 = rowBase + wm + mi * 16 + g;
        int row1 = row0 + 8;
#pragma unroll
        for (int ni = 0; ni < 8; ni++) {
            int col = colBase + wn + ni * 8 + t * 2;
            if (row0 < M)
                *(float2*)(C + (size_t)row0 * N + col) =
                    make_float2(acc[mi][ni][0], acc[mi][ni][1]);
            if (row1 < M)
                *(float2*)(C + (size_t)row1 * N + col) =
                    make_float2(acc[mi][ni][2], acc[mi][ni][3]);
        }
    }
}

// ---------------- aggregation layer 1: 512 features, 1 warp / node ----------------
__global__ __launch_bounds__(256)
void agg1_kernel(const float* __restrict__ b1) {
    int node = blockIdx.x * 8 + (threadIdx.x >> 5);
    if (node >= N_NODES) return;
    int lane = threadIdx.x & 31;
    const float4* h = (const float4*)g_h1;
    float dc = g_dis[node];

    float4 acc[4];
#pragma unroll
    for (int i = 0; i < 4; i++) {
        float4 v = h[(size_t)node * 128 + lane + i * 32];
        acc[i] = make_float4(v.x * dc, v.y * dc, v.z * dc, v.w * dc);
    }
    int beg = g_rowptr[node], end = g_rowptr[node + 1];
    for (int e = beg; e < end; e++) {
        int r = g_src[e];
        float w = g_wgt[e];
        const float4* hr = h + (size_t)r * 128;
#pragma unroll
        for (int i = 0; i < 4; i++) {
            float4 v = hr[lane + i * 32];
            acc[i].x += w * v.x; acc[i].y += w * v.y;
            acc[i].z += w * v.z; acc[i].w += w * v.w;
        }
    }
    float4* out = (float4*)g_a1;
    const float4* bb4 = (const float4*)b1;
#pragma unroll
    for (int i = 0; i < 4; i++) {
        float4 bb = bb4[lane + i * 32];
        float4 o;
        o.x = fmaxf(dc * acc[i].x + bb.x, 0.f);
        o.y = fmaxf(dc * acc[i].y + bb.y, 0.f);
        o.z = fmaxf(dc * acc[i].z + bb.z, 0.f);
        o.w = fmaxf(dc * acc[i].w + bb.w, 0.f);
        out[(size_t)node * 128 + lane + i * 32] = o;
    }
}

// ---------------- aggregation layer 2 fused with FC(128->14)+sigmoid ----------------
__global__ __launch_bounds__(256)
void agg2_fc_kernel(const float* __restrict__ b2, const float* __restrict__ Wfc,
                    const float* __restrict__ bfc, float* __restrict__ out) {
    __shared__ float sh[8][128];
    __shared__ float sWfc[D2 * DOUT];
    for (int i = threadIdx.x; i < D2 * DOUT; i += blockDim.x) sWfc[i] = Wfc[i];
    __syncthreads();

    int wid = threadIdx.x >> 5;
    int lane = threadIdx.x & 31;
    int node = blockIdx.x * 8 + wid;

    if (node < N_NODES) {
        const float4* h = (const float4*)g_h2;
        float dc = g_dis[node];
        float4 v = h[(size_t)node * 32 + lane];
        float4 acc = make_float4(v.x * dc, v.y * dc, v.z * dc, v.w * dc);
        int beg = g_rowptr[node], end = g_rowptr[node + 1];
        for (int e = beg; e < end; e++) {
            int r = g_src[e];
            float w = g_wgt[e];
            float4 u = h[(size_t)r * 32 + lane];
            acc.x += w * u.x; acc.y += w * u.y; acc.z += w * u.z; acc.w += w * u.w;
        }
        float4 bb = ((const float4*)b2)[lane];
        sh[wid][lane * 4 + 0] = fmaxf(dc * acc.x + bb.x, 0.f);
        sh[wid][lane * 4 + 1] = fmaxf(dc * acc.y + bb.y, 0.f);
        sh[wid][lane * 4 + 2] = fmaxf(dc * acc.z + bb.z, 0.f);
        sh[wid][lane * 4 + 3] = fmaxf(dc * acc.w + bb.w, 0.f);
    }
    __syncwarp();
    if (node < N_NODES && lane < DOUT) {
        float s = bfc[lane];
#pragma unroll 8
        for (int d = 0; d < D2; d++) s += sh[wid][d] * sWfc[d * DOUT + lane];
        out[(size_t)node * DOUT + lane] = 1.f / (1.f + expf(-s));
    }
}

// ---------------- launch ----------------
// GEMM1 stays at our launch #4 (profiled slot).
extern "C" void kernel_launch(void* const* d_in, const int* in_sizes, int n_in,
                              void* d_out, int out_size) {
    const float* x   = (const float*)d_in[0];
    const void*  eix = d_in[1];
    const float* ew  = (const float*)d_in[2];
    const float* W1  = (const float*)d_in[3];
    const float* b1  = (const float*)d_in[4];
    const float* W2  = (const float*)d_in[5];
    const float* b2  = (const float*)d_in[6];
    const float* Wfc = (const float*)d_in[7];
    const float* bfc = (const float*)d_in[8];
    float* out = (float*)d_out;

    float *h1p, *a1p, *h2p;
    cudaGetSymbolAddress((void**)&h1p, g_h1);
    cudaGetSymbolAddress((void**)&a1p, g_a1);
    cudaGetSymbolAddress((void**)&h2p, g_h2);

    cudaFuncSetAttribute(tf32gemm, cudaFuncAttributeMaxDynamicSharedMemorySize,
                         GEMM_SMEM_BYTES);

    const int TB = 256;
    detect_idx_kernel<<<1, 32>>>(eix);                              // 1
    init_kernel<<<(N_NODES + TB - 1) / TB, TB>>>();                 // 2
    edge_deg_kernel<<<(N_EDGES + TB - 1) / TB, TB>>>(eix, ew);      // 3

    dim3 g1(D1 / BN, (N_NODES + BM - 1) / BM);
    tf32gemm<<<g1, 256, GEMM_SMEM_BYTES>>>(x, W1, h1p, N_NODES, D0, D1);  // 4 <- ncu

    dis_kernel<<<(N_NODES + TB - 1) / TB, TB>>>();                  // 5
    scan_kernel<<<1, 1024>>>();                                     // 6
    scatter_kernel<<<(N_EDGES + TB - 1) / TB, TB>>>(eix, ew);       // 7

    agg1_kernel<<<(N_NODES + 7) / 8, 256>>>(b1);                    // 8

    dim3 g2(D2 / BN, (N_NODES + BM - 1) / BM);
    tf32gemm<<<g2, 256, GEMM_SMEM_BYTES>>>(a1p, W2, h2p, N_NODES, D1, D2);  // 9

    agg2_fc_kernel<<<(N_NODES + 7) / 8, 256>>>(b2, Wfc, bfc, out);  // 10
}

// round 8
// speedup vs baseline: 1.4169x; 1.3572x over previous
#include <cuda_runtime.h>
#include <cuda_bf16.h>
#include <cstdint>
#include <math.h>

#define N_NODES 50000
#define N_EDGES 800000
#define D0 1024
#define D1 512
#define D2 128
#define DOUT 14

// ---------------- scratch (device globals; no allocs allowed) ----------------
__device__ float    g_deg[N_NODES];
__device__ float    g_dis[N_NODES];
__device__ int      g_cnt[N_NODES];
__device__ int      g_rowptr[N_NODES + 1];
__device__ int      g_src[N_EDGES];
__device__ float    g_wgt[N_EDGES];
__device__ int      g_is64;
// bf16 storage (packed pairs in uint32)
__device__ uint32_t g_xb [(size_t)N_NODES * (D0 / 2)];   // X bf16, row-major
__device__ uint32_t g_w1b[(D0 / 2) * D1];                // W1 bf16, k-pair interleaved [k2][n]
__device__ uint32_t g_w2b[(D1 / 2) * D2];                // W2 likewise
__device__ uint32_t g_h1b[(size_t)N_NODES * (D1 / 2)];   // X@W1, bf16
__device__ uint32_t g_a1b[(size_t)N_NODES * (D1 / 2)];   // relu(agg+b1), bf16
__device__ uint32_t g_h2b[(size_t)N_NODES * (D2 / 2)];   // a1@W2, bf16

// ---------------- small helpers ----------------
__device__ __forceinline__ uint32_t pack_bf2(float lo, float hi) {
    uint32_t w;
    asm("cvt.rn.bf16x2.f32 %0, %1, %2;" : "=r"(w) : "f"(hi), "f"(lo));
    return w;
}
__device__ __forceinline__ float2 bf2f(uint32_t w) {
    float2 r;
    r.x = __uint_as_float(w << 16);
    r.y = __uint_as_float(w & 0xffff0000u);
    return r;
}

// ---------------- edge-index dtype detection (int64 vs int32) ----------------
__global__ void detect_idx_kernel(const void* eidx) {
    int lane = threadIdx.x & 31;
    const int* p = (const int*)eidx;
    int bad = 0;
#pragma unroll
    for (int k = 0; k < 32; k++) bad |= p[2 * (k * 32 + lane) + 1];
    unsigned m = __ballot_sync(0xffffffffu, bad != 0);
    if (lane == 0) g_is64 = (m == 0) ? 1 : 0;
}

__device__ __forceinline__ int get_idx(const void* base, long i) {
    if (g_is64) return (int)((const long long*)base)[i];
    return ((const int*)base)[i];
}

// ---------------- conversions ----------------
// X fp32 -> bf16 row-major (A matrices keep consecutive-k adjacency).
__global__ void conv_x_kernel(const float* __restrict__ x) {
    size_t i = (size_t)blockIdx.x * blockDim.x + threadIdx.x;  // float4 index
    size_t total = (size_t)N_NODES * (D0 / 4);
    if (i < total) {
        float4 v = ((const float4*)x)[i];
        g_xb[i * 2]     = pack_bf2(v.x, v.y);
        g_xb[i * 2 + 1] = pack_bf2(v.z, v.w);
    }
}

// W fp32 [K][N] -> bf16 k-pair interleaved words [K/2][N]
__global__ void conv_w_kernel(const float* __restrict__ W, uint32_t* __restrict__ out,
                              int K, int N) {
    int i = blockIdx.x * blockDim.x + threadIdx.x;
    if (i < (K / 2) * N) {
        int k2 = i / N, n = i - k2 * N;
        out[i] = pack_bf2(W[(2 * k2) * N + n], W[(2 * k2 + 1) * N + n]);
    }
}

// ---------------- degree / normalization / CSR build ----------------
__global__ void init_kernel() {
    int i = blockIdx.x * blockDim.x + threadIdx.x;
    if (i < N_NODES) { g_deg[i] = 1.0f; g_cnt[i] = 0; }
}

__global__ void edge_deg_kernel(const void* eidx, const float* __restrict__ ew) {
    int e = blockIdx.x * blockDim.x + threadIdx.x;
    if (e < N_EDGES) {
        int c = get_idx(eidx, (long)N_EDGES + e);
        atomicAdd(&g_deg[c], ew[e]);
        atomicAdd(&g_cnt[c], 1);
    }
}

__global__ void dis_kernel() {
    int i = blockIdx.x * blockDim.x + threadIdx.x;
    if (i < N_NODES) g_dis[i] = rsqrtf(g_deg[i]);
}

__global__ void scan_kernel() {
    __shared__ int part[1024];
    int tid = threadIdx.x;
    const int chunk = (N_NODES + 1023) / 1024;
    int start = tid * chunk;
    int end = start + chunk; if (end > N_NODES) end = N_NODES;
    int s = 0;
    for (int i = start; i < end; i++) s += g_cnt[i];
    part[tid] = s;
    __syncthreads();
    if (tid == 0) {
        int run = 0;
        for (int i = 0; i < 1024; i++) { int v = part[i]; part[i] = run; run += v; }
        g_rowptr[N_NODES] = run;
    }
    __syncthreads();
    int run = part[tid];
    for (int i = start; i < end; i++) {
        g_rowptr[i] = run;
        run += g_cnt[i];
        g_cnt[i] = 0;
    }
}

__global__ void scatter_kernel(const void* eidx, const float* __restrict__ ew) {
    int e = blockIdx.x * blockDim.x + threadIdx.x;
    if (e < N_EDGES) {
        int r = get_idx(eidx, e);
        int c = get_idx(eidx, (long)N_EDGES + e);
        int pos = g_rowptr[c] + atomicAdd(&g_cnt[c], 1);
        g_src[pos] = r;
        g_wgt[pos] = ew[e] * g_dis[r];
    }
}

// ---------------- bf16 tensor-core GEMM, cp.async 4-stage ----------------
// BM=128, BN=128, BK=32 (bf16); 256 threads = 8 warps (4x2); warp tile 32x64.
// mma.m16n8k16.bf16, fp32 accum. A bf16 row-major, B bf16 k-pair interleaved.
#define BM 128
#define BN 128
#define BK 32
#define STAGES 4
#define AW 20                         // A row stride in words (16 + 4 pad): banks 20g+t bijective
#define BW 136                        // B row stride in words (128 + 8 pad): banks 8t+g bijective
#define A_SZW (BM * AW)               // 2560 words
#define B_SZW ((BK / 2) * BW)         // 2176 words
#define STG_SZW (A_SZW + B_SZW)       // 4736 words
#define GEMM_SMEM_BYTES (STAGES * STG_SZW * 4)   // 75776 B

__device__ __forceinline__ void mma_bf16(float* d, const uint32_t* a, const uint32_t* b) {
    asm volatile(
        "mma.sync.aligned.m16n8k16.row.col.f32.bf16.bf16.f32 "
        "{%0,%1,%2,%3}, {%4,%5,%6,%7}, {%8,%9}, {%0,%1,%2,%3};"
        : "+f"(d[0]), "+f"(d[1]), "+f"(d[2]), "+f"(d[3])
        : "r"(a[0]), "r"(a[1]), "r"(a[2]), "r"(a[3]), "r"(b[0]), "r"(b[1]));
}

__device__ __forceinline__ void cp_async16(void* smem_ptr, const void* gptr, int srcsize) {
    unsigned int sa = (unsigned int)__cvta_generic_to_shared(smem_ptr);
    asm volatile("cp.async.cg.shared.global [%0], [%1], 16, %2;\n"
                 :: "r"(sa), "l"(gptr), "r"(srcsize));
}

// One BK=32 stage: A 128x16 words, B 16x128 words; 2 cp.async each per thread.
__device__ __forceinline__ void load_stage_bf(
    const uint32_t* __restrict__ Agm, const uint32_t* __restrict__ Bgm,
    int M, int Kw, int N, int rowBase, int colBase, int k0w,
    uint32_t* As, uint32_t* Bs, int tid)
{
#pragma unroll
    for (int p = 0; p < 2; p++) {
        int idx = p * 256 + tid;
        int r = idx >> 2, c = idx & 3;
        int gr = rowBase + r;
        int sz = (gr < M) ? 16 : 0;
        int grc = (gr < M) ? gr : 0;
        cp_async16(&As[r * AW + c * 4], Agm + (size_t)grc * Kw + k0w + c * 4, sz);
    }
#pragma unroll
    for (int p = 0; p < 2; p++) {
        int idx = p * 256 + tid;
        int r = idx >> 5, c = idx & 31;
        cp_async16(&Bs[r * BW + c * 4], Bgm + (size_t)(k0w + r) * N + colBase + c * 4, 16);
    }
}

// C written as bf16 pair-words [M][N/2].
__global__ __launch_bounds__(256, 2)
void bf16gemm(const uint32_t* __restrict__ Agm, const uint32_t* __restrict__ Bgm,
              uint32_t* __restrict__ Cw, int M, int K, int N) {
    extern __shared__ uint32_t smem_dyn[];

    int tid = threadIdx.x;
    int warp = tid >> 5, lane = tid & 31;
    int g = lane >> 2, t = lane & 3;
    int wm = (warp >> 1) * 32;
    int wn = (warp & 1) * 64;

    int rowBase = blockIdx.y * BM;
    int colBase = blockIdx.x * BN;
    int Kw = K / 2, Nw = N / 2;

    float acc[2][8][4];
#pragma unroll
    for (int mi = 0; mi < 2; mi++)
#pragma unroll
        for (int ni = 0; ni < 8; ni++)
#pragma unroll
            for (int r = 0; r < 4; r++) acc[mi][ni][r] = 0.f;

    int niter = K / BK;

#pragma unroll
    for (int p = 0; p < STAGES - 1; p++) {
        if (p < niter)
            load_stage_bf(Agm, Bgm, M, Kw, N, rowBase, colBase, p * (BK / 2),
                          smem_dyn + p * STG_SZW, smem_dyn + p * STG_SZW + A_SZW, tid);
        asm volatile("cp.async.commit_group;\n");
    }

    int s_cur = 0, s_load = STAGES - 1;

    for (int i = 0; i < niter; i++) {
        asm volatile("cp.async.wait_group 2;\n");
        __syncthreads();

        int inext = i + STAGES - 1;
        if (inext < niter)
            load_stage_bf(Agm, Bgm, M, Kw, N, rowBase, colBase, inext * (BK / 2),
                          smem_dyn + s_load * STG_SZW,
                          smem_dyn + s_load * STG_SZW + A_SZW, tid);
        asm volatile("cp.async.commit_group;\n");

        const uint32_t* As = smem_dyn + s_cur * STG_SZW;
        const uint32_t* Bs = As + A_SZW;
#pragma unroll
        for (int s = 0; s < 2; s++) {     // two k16 steps per BK=32
            uint32_t a[2][4];
#pragma unroll
            for (int mi = 0; mi < 2; mi++) {
                int row = wm + mi * 16;
                a[mi][0] = As[(row + g    ) * AW + s * 8 + t    ];
                a[mi][1] = As[(row + g + 8) * AW + s * 8 + t    ];
                a[mi][2] = As[(row + g    ) * AW + s * 8 + t + 4];
                a[mi][3] = As[(row + g + 8) * AW + s * 8 + t + 4];
            }
#pragma unroll
            for (int h = 0; h < 2; h++) {
                uint32_t b[4][2];
#pragma unroll
                for (int nj = 0; nj < 4; nj++) {
                    int col = wn + (h * 4 + nj) * 8;
                    b[nj][0] = Bs[(s * 8 + t    ) * BW + col + g];
                    b[nj][1] = Bs[(s * 8 + t + 4) * BW + col + g];
                }
#pragma unroll
                for (int mi = 0; mi < 2; mi++)
#pragma unroll
                    for (int nj = 0; nj < 4; nj++)
                        mma_bf16(acc[mi][h * 4 + nj], a[mi], b[nj]);
            }
        }

        s_cur  = (s_cur  + 1 == STAGES) ? 0 : s_cur  + 1;
        s_load = (s_load + 1 == STAGES) ? 0 : s_load + 1;
    }

    // epilogue: pack (c0,c1)/(c2,c3) into bf16 pair words
#pragma unroll
    for (int mi = 0; mi < 2; mi++) {
        int row0 = rowBase + wm + mi * 16 + g;
        int row1 = row0 + 8;
#pragma unroll
        for (int ni = 0; ni < 8; ni++) {
            int cw = (colBase + wn + ni * 8) / 2 + t;
            if (row0 < M)
                Cw[(size_t)row0 * Nw + cw] = pack_bf2(acc[mi][ni][0], acc[mi][ni][1]);
            if (row1 < M)
                Cw[(size_t)row1 * Nw + cw] = pack_bf2(acc[mi][ni][2], acc[mi][ni][3]);
        }
    }
}

// ---------------- aggregation layer 1: bf16 h1, fp32 accum, bf16 out ----------
__global__ __launch_bounds__(256)
void agg1_kernel(const float* __restrict__ b1) {
    int node = blockIdx.x * 8 + (threadIdx.x >> 5);
    if (node >= N_NODES) return;
    int lane = threadIdx.x & 31;
    const uint4* h = (const uint4*)g_h1b;   // 64 uint4 per row
    float dc = g_dis[node];

    float2 acc[8];
    {
        uint4 v0 = h[(size_t)node * 64 + lane];
        uint4 v1 = h[(size_t)node * 64 + lane + 32];
        float2 f;
        f = bf2f(v0.x); acc[0] = make_float2(f.x * dc, f.y * dc);
        f = bf2f(v0.y); acc[1] = make_float2(f.x * dc, f.y * dc);
        f = bf2f(v0.z); acc[2] = make_float2(f.x * dc, f.y * dc);
        f = bf2f(v0.w); acc[3] = make_float2(f.x * dc, f.y * dc);
        f = bf2f(v1.x); acc[4] = make_float2(f.x * dc, f.y * dc);
        f = bf2f(v1.y); acc[5] = make_float2(f.x * dc, f.y * dc);
        f = bf2f(v1.z); acc[6] = make_float2(f.x * dc, f.y * dc);
        f = bf2f(v1.w); acc[7] = make_float2(f.x * dc, f.y * dc);
    }
    int beg = g_rowptr[node], end = g_rowptr[node + 1];
    for (int e = beg; e < end; e++) {
        int r = g_src[e];
        float w = g_wgt[e];
        uint4 u0 = h[(size_t)r * 64 + lane];
        uint4 u1 = h[(size_t)r * 64 + lane + 32];
        float2 f;
        f = bf2f(u0.x); acc[0].x += w * f.x; acc[0].y += w * f.y;
        f = bf2f(u0.y); acc[1].x += w * f.x; acc[1].y += w * f.y;
        f = bf2f(u0.z); acc[2].x += w * f.x; acc[2].y += w * f.y;
        f = bf2f(u0.w); acc[3].x += w * f.x; acc[3].y += w * f.y;
        f = bf2f(u1.x); acc[4].x += w * f.x; acc[4].y += w * f.y;
        f = bf2f(u1.y); acc[5].x += w * f.x; acc[5].y += w * f.y;
        f = bf2f(u1.z); acc[6].x += w * f.x; acc[6].y += w * f.y;
        f = bf2f(u1.w); acc[7].x += w * f.x; acc[7].y += w * f.y;
    }
    // bias + relu + pack
    const float2* bb = (const float2*)b1;   // 256 float2
    uint32_t ow[8];
#pragma unroll
    for (int j = 0; j < 8; j++) {
        int wordIdx = (j < 4) ? (4 * lane + j) : (128 + 4 * lane + (j - 4));
        float2 bv = bb[wordIdx];
        float lo = fmaxf(dc * acc[j].x + bv.x, 0.f);
        float hi = fmaxf(dc * acc[j].y + bv.y, 0.f);
        ow[j] = pack_bf2(lo, hi);
    }
    uint4* out = (uint4*)g_a1b;
    out[(size_t)node * 64 + lane]      = make_uint4(ow[0], ow[1], ow[2], ow[3]);
    out[(size_t)node * 64 + lane + 32] = make_uint4(ow[4], ow[5], ow[6], ow[7]);
}

// ---------------- aggregation layer 2 (bf16 h2) fused with FC+sigmoid --------
__global__ __launch_bounds__(256)
void agg2_fc_kernel(const float* __restrict__ b2, const float* __restrict__ Wfc,
                    const float* __restrict__ bfc, float* __restrict__ out) {
    __shared__ float sh[8][128];
    __shared__ float sWfc[D2 * DOUT];
    for (int i = threadIdx.x; i < D2 * DOUT; i += blockDim.x) sWfc[i] = Wfc[i];
    __syncthreads();

    int wid = threadIdx.x >> 5;
    int lane = threadIdx.x & 31;
    int node = blockIdx.x * 8 + wid;

    if (node < N_NODES) {
        const uint2* h = (const uint2*)g_h2b;   // 32 uint2 per row (64 words)
        float dc = g_dis[node];
        uint2 v = h[(size_t)node * 32 + lane];
        float2 f0 = bf2f(v.x), f1 = bf2f(v.y);
        float2 acc0 = make_float2(f0.x * dc, f0.y * dc);
        float2 acc1 = make_float2(f1.x * dc, f1.y * dc);
        int beg = g_rowptr[node], end = g_rowptr[node + 1];
        for (int e = beg; e < end; e++) {
            int r = g_src[e];
            float w = g_wgt[e];
            uint2 u = h[(size_t)r * 32 + lane];
            float2 g0 = bf2f(u.x), g1 = bf2f(u.y);
            acc0.x += w * g0.x; acc0.y += w * g0.y;
            acc1.x += w * g1.x; acc1.y += w * g1.y;
        }
        const float2* bb = (const float2*)b2;   // 64 float2
        float2 b0 = bb[2 * lane], b1v = bb[2 * lane + 1];
        sh[wid][lane * 4 + 0] = fmaxf(dc * acc0.x + b0.x, 0.f);
        sh[wid][lane * 4 + 1] = fmaxf(dc * acc0.y + b0.y, 0.f);
        sh[wid][lane * 4 + 2] = fmaxf(dc * acc1.x + b1v.x, 0.f);
        sh[wid][lane * 4 + 3] = fmaxf(dc * acc1.y + b1v.y, 0.f);
    }
    __syncwarp();
    if (node < N_NODES && lane < DOUT) {
        float s = bfc[lane];
#pragma unroll 8
        for (int d = 0; d < D2; d++) s += sh[wid][d] * sWfc[d * DOUT + lane];
        out[(size_t)node * DOUT + lane] = 1.f / (1.f + expf(-s));
    }
}

// ---------------- launch ----------------
// GEMM1 stays at our launch #4 (profiled slot): detect, conv_x, conv_w1, GEMM1.
extern "C" void kernel_launch(void* const* d_in, const int* in_sizes, int n_in,
                              void* d_out, int out_size) {
    const float* x   = (const float*)d_in[0];
    const void*  eix = d_in[1];
    const float* ew  = (const float*)d_in[2];
    const float* W1  = (const float*)d_in[3];
    const float* b1  = (const float*)d_in[4];
    const float* W2  = (const float*)d_in[5];
    const float* b2  = (const float*)d_in[6];
    const float* Wfc = (const float*)d_in[7];
    const float* bfc = (const float*)d_in[8];
    float* out = (float*)d_out;

    uint32_t *xb, *w1b, *w2b, *h1b, *a1b, *h2b;
    cudaGetSymbolAddress((void**)&xb,  g_xb);
    cudaGetSymbolAddress((void**)&w1b, g_w1b);
    cudaGetSymbolAddress((void**)&w2b, g_w2b);
    cudaGetSymbolAddress((void**)&h1b, g_h1b);
    cudaGetSymbolAddress((void**)&a1b, g_a1b);
    cudaGetSymbolAddress((void**)&h2b, g_h2b);

    cudaFuncSetAttribute(bf16gemm, cudaFuncAttributeMaxDynamicSharedMemorySize,
                         GEMM_SMEM_BYTES);

    const int TB = 256;
    detect_idx_kernel<<<1, 32>>>(eix);                                        // 1
    {
        size_t nv = (size_t)N_NODES * (D0 / 4);
        conv_x_kernel<<<(int)((nv + TB - 1) / TB), TB>>>(x);                  // 2
    }
    conv_w_kernel<<<((D0 / 2) * D1 + TB - 1) / TB, TB>>>(W1, w1b, D0, D1);    // 3

    dim3 g1(D1 / BN, (N_NODES + BM - 1) / BM);
    bf16gemm<<<g1, 256, GEMM_SMEM_BYTES>>>(xb, w1b, h1b, N_NODES, D0, D1);    // 4 <- ncu

    init_kernel<<<(N_NODES + TB - 1) / TB, TB>>>();                           // 5
    edge_deg_kernel<<<(N_EDGES + TB - 1) / TB, TB>>>(eix, ew);                // 6
    dis_kernel<<<(N_NODES + TB - 1) / TB, TB>>>();                            // 7
    scan_kernel<<<1, 1024>>>();                                               // 8
    scatter_kernel<<<(N_EDGES + TB - 1) / TB, TB>>>(eix, ew);                 // 9

    agg1_kernel<<<(N_NODES + 7) / 8, 256>>>(b1);                              // 10

    conv_w_kernel<<<((D1 / 2) * D2 + TB - 1) / TB, TB>>>(W2, w2b, D1, D2);    // 11

    dim3 g2(D2 / BN, (N_NODES + BM - 1) / BM);
    bf16gemm<<<g2, 256, GEMM_SMEM_BYTES>>>(a1b, w2b, h2b, N_NODES, D1, D2);   // 12

    agg2_fc_kernel<<<(N_NODES + 7) / 8, 256>>>(b2, Wfc, bfc, out);            // 13
}